// round 8
// baseline (speedup 1.0000x reference)
#include <cuda_runtime.h>

// ESH sampler: B rows, D=64, n_steps of 2 half-steps each.
// Layout: 8 lanes per row (group), 4 rows per warp, 8 elems (2 float4) per lane.
// Lane-in-group p owns float4 chunks {p, p+8}.
//
// Grad is evaluated at the SAME x in the 2nd half-step of step s and the 1st
// half-step of step s+1, so g and its scalars are computed once per drift and
// reused (value-identical to reference). u carried unnormalized with scalar
// scale `us`; materialized at store time. x stored right after the drift.
// 32-bit output offsets (out < 2^32 elements). 4 blocks/SM — measured optimum;
// higher occupancy (5-6 blocks) regressed DRAM feed (cross-CTA store-queue
// contention), see R3/R5.

__device__ __forceinline__ float grp_sum8(float v) {
    v += __shfl_xor_sync(0xffffffffu, v, 1);
    v += __shfl_xor_sync(0xffffffffu, v, 2);
    v += __shfl_xor_sync(0xffffffffu, v, 4);
    return v;
}

// g = prec*x and all scalars that depend only on g.
__device__ __forceinline__ void compute_g(
    const float4 (&xv)[2], const float4 (&pv)[2],
    float4 (&g)[2], float& rs, float& gn, float& t2, float& Bc, float ed)
{
    float gsq = 0.0f;
#pragma unroll
    for (int j = 0; j < 2; j++) {
        g[j].x = pv[j].x * xv[j].x; gsq = fmaf(g[j].x, g[j].x, gsq);
        g[j].y = pv[j].y * xv[j].y; gsq = fmaf(g[j].y, g[j].y, gsq);
        g[j].z = pv[j].z * xv[j].z; gsq = fmaf(g[j].z, g[j].z, gsq);
        g[j].w = pv[j].w * xv[j].w; gsq = fmaf(g[j].w, g[j].w, gsq);
    }
    gsq = grp_sum8(gsq);
    rs = rsqrtf(fmaxf(gsq, 1e-20f));     // == 1/||g||
    gn = fminf(gsq * rs, 10.0f);         // clamped norm
    float t = __expf(-ed * gn);          // exp(-e*g/d)
    t2 = t * t;
    Bc = 2.0f * t;
}

// Momentum/r update given precomputed g and scalars.
__device__ __forceinline__ void update_ur(
    const float4 (&g)[2], float4 (&uv)[2],
    float& us, float& r, float rs, float gn, float t2, float Bc, float ed)
{
    float ugr = 0.0f;
#pragma unroll
    for (int j = 0; j < 2; j++) {
        ugr = fmaf(uv[j].x, g[j].x, ugr);
        ugr = fmaf(uv[j].y, g[j].y, ugr);
        ugr = fmaf(uv[j].z, g[j].z, ugr);
        ugr = fmaf(uv[j].w, g[j].w, ugr);
    }
    ugr = grp_sum8(ugr);

    float ude  = -(us * ugr) * rs;            // u_true . grad_e
    float A2   = (ude - 1.0f) * t2;
    float opu  = 1.0f + ude;
    float A    = opu + A2;
    bool  cond = ude > -0.999f;
    float Bs   = cond ? Bc * us : 0.0f;                  // coeff on u_raw
    float Cc   = cond ? fmaf(Bc, ude, -A) * rs : rs;     // coeff on g

    float nsq = 0.0f;
#pragma unroll
    for (int j = 0; j < 2; j++) {
        float un;
        un = fmaf(Cc, g[j].x, Bs * uv[j].x); uv[j].x = un; nsq = fmaf(un, un, nsq);
        un = fmaf(Cc, g[j].y, Bs * uv[j].y); uv[j].y = un; nsq = fmaf(un, un, nsq);
        un = fmaf(Cc, g[j].z, Bs * uv[j].z); uv[j].z = un; nsq = fmaf(un, un, nsq);
        un = fmaf(Cc, g[j].w, Bs * uv[j].w); uv[j].w = un; nsq = fmaf(un, un, nsq);
    }
    nsq = grp_sum8(nsq);
    us  = rsqrtf(fmaxf(nsq, 1e-20f));         // u_true = us * u_raw

    float Z  = opu - A2;
    float dr = cond ? fmaf(ed, gn, __logf(0.5f * fmaxf(Z, 1e-10f)))
                    : -ed * gn;
    r += dr;
}

__global__ __launch_bounds__(256, 4)
void esh_kernel(const float* __restrict__ x0,
                const float* __restrict__ u0,
                const float* __restrict__ prec,
                const float* __restrict__ eps_p,
                const int* __restrict__ nsteps_p,
                float* __restrict__ out,
                int B)
{
    const int tid  = threadIdx.x;
    const int lane = tid & 31;
    const int p    = lane & 7;       // lane within group (8 per row)
    const int grp  = lane >> 3;      // 0..3 : row within warp
    const int warp = tid >> 5;       // 0..7
    const int row  = blockIdx.x * 32 + warp * 4 + grp;
    if (row >= B) return;

    const float eps = *eps_p;
    const int n_steps = *nsteps_p;
    const float ed = (0.5f * eps) * (1.0f / 64.0f);  // e/d, e = eps/2

    float4 xv[2], uv[2], pv[2];
    {
        const float4* xp = reinterpret_cast<const float4*>(x0 + (size_t)row * 64);
        const float4* up = reinterpret_cast<const float4*>(u0 + (size_t)row * 64);
        const float4* pp = reinterpret_cast<const float4*>(prec);
#pragma unroll
        for (int j = 0; j < 2; j++) {
            xv[j] = xp[p + 8 * j];
            uv[j] = up[p + 8 * j];
            pv[j] = pp[p + 8 * j];
        }
    }
    float r = 0.0f;
    float us = 1.0f;   // u_true = us * uv

    // 32-bit addressing: total output < 2^32 floats.
    const unsigned rowstride4 = (unsigned)B * 16u;             // float4s per step per array
    const unsigned XN4 = (unsigned)(n_steps + 1) * rowstride4; // float4s in traj_x
    float4* const o4 = reinterpret_cast<float4*>(out);

    unsigned ox_off = (unsigned)row * 16u + (unsigned)p;       // float4 index into traj_x
    unsigned ou_off = XN4 + ox_off;                            // float4 index into traj_u
    unsigned r_off  = 8u * XN4 + (unsigned)row;                // float index into traj_r

    // step 0: x0, u0, r0=0
#pragma unroll
    for (int j = 0; j < 2; j++) {
        __stcs(&o4[ox_off + 8u * j], xv[j]);
        __stcs(&o4[ou_off + 8u * j], uv[j]);
    }
    if (p == 0) __stcs(&out[r_off], 0.0f);

    // gradient state at current x (reused across step boundary)
    float4 g[2];
    float rs, gn, t2, Bc;
    compute_g(xv, pv, g, rs, gn, t2, Bc, ed);

    for (int s = 1; s <= n_steps; s++) {
        // first half-step: uses g at undrifted x (carried over)
        update_ur(g, uv, us, r, rs, gn, t2, Bc, ed);

        // drift: x += eps * u_true ; x is final for this step -> store now
        {
            const float c = eps * us;
#pragma unroll
            for (int j = 0; j < 2; j++) {
                xv[j].x = fmaf(c, uv[j].x, xv[j].x);
                xv[j].y = fmaf(c, uv[j].y, xv[j].y);
                xv[j].z = fmaf(c, uv[j].z, xv[j].z);
                xv[j].w = fmaf(c, uv[j].w, xv[j].w);
            }
        }
        ox_off += rowstride4;
#pragma unroll
        for (int j = 0; j < 2; j++) __stcs(&o4[ox_off + 8u * j], xv[j]);

        // gradient at drifted x (also serves next iteration's first half-step)
        compute_g(xv, pv, g, rs, gn, t2, Bc, ed);

        // second half-step
        update_ur(g, uv, us, r, rs, gn, t2, Bc, ed);

        ou_off += rowstride4;
        r_off  += (unsigned)B;
        // materialize normalized u and store
#pragma unroll
        for (int j = 0; j < 2; j++) {
            float4 w;
            w.x = us * uv[j].x; w.y = us * uv[j].y;
            w.z = us * uv[j].z; w.w = us * uv[j].w;
            uv[j] = w;
            __stcs(&o4[ou_off + 8u * j], w);
        }
        us = 1.0f;
        if (p == 0) __stcs(&out[r_off], r);
    }
}

extern "C" void kernel_launch(void* const* d_in, const int* in_sizes, int n_in,
                              void* d_out, int out_size)
{
    const float* x0     = (const float*)d_in[0];
    const float* u0     = (const float*)d_in[1];
    const float* prec   = (const float*)d_in[2];
    const float* eps_p  = (const float*)d_in[3];
    const int*   nsteps = (const int*)d_in[4];
    float* out = (float*)d_out;

    int B = in_sizes[0] / 64;
    int rows_per_block = 32;  // 256 threads, 8 warps, 4 rows/warp
    int grid = (B + rows_per_block - 1) / rows_per_block;
    esh_kernel<<<grid, 256>>>(x0, u0, prec, eps_p, nsteps, out, B);
}

// round 9
// speedup vs baseline: 1.3853x; 1.3853x over previous
#include <cuda_runtime.h>

// ESH sampler: B rows, D=64, n_steps of 2 half-steps each.
// Layout: 8 lanes per row (group), 4 rows per warp, 8 elems (2 float4) per lane.
// Lane-in-group p owns float4 chunks {p, p+8}.
//
// Grad is evaluated at the SAME x in the 2nd half-step of step s and the 1st
// half-step of step s+1 (x only changes at the drift), so g and its scalars
// are computed once per drift and reused — value-identical to the reference.
// u carried unnormalized with scalar scale `us`; materialized at store time.
// x stored right after the drift to spread DRAM traffic.
// size_t pointer addressing + bounds(256,4): the measured-stable optimum
// (32-bit offsets and higher block caps both regressed; see R5/R7 notes).

__device__ __forceinline__ float grp_sum8(float v) {
    v += __shfl_xor_sync(0xffffffffu, v, 1);
    v += __shfl_xor_sync(0xffffffffu, v, 2);
    v += __shfl_xor_sync(0xffffffffu, v, 4);
    return v;
}

// g = prec*x and all scalars that depend only on g.
__device__ __forceinline__ void compute_g(
    const float4 (&xv)[2], const float4 (&pv)[2],
    float4 (&g)[2], float& rs, float& gn, float& t2, float& Bc, float ed)
{
    float gsq = 0.0f;
#pragma unroll
    for (int j = 0; j < 2; j++) {
        g[j].x = pv[j].x * xv[j].x; gsq = fmaf(g[j].x, g[j].x, gsq);
        g[j].y = pv[j].y * xv[j].y; gsq = fmaf(g[j].y, g[j].y, gsq);
        g[j].z = pv[j].z * xv[j].z; gsq = fmaf(g[j].z, g[j].z, gsq);
        g[j].w = pv[j].w * xv[j].w; gsq = fmaf(g[j].w, g[j].w, gsq);
    }
    gsq = grp_sum8(gsq);
    rs = rsqrtf(fmaxf(gsq, 1e-20f));     // == 1/||g||
    gn = fminf(gsq * rs, 10.0f);         // clamped norm
    float t = __expf(-ed * gn);          // exp(-e*g/d)
    t2 = t * t;
    Bc = 2.0f * t;
}

// Momentum/r update given precomputed g and scalars.
__device__ __forceinline__ void update_ur(
    const float4 (&g)[2], float4 (&uv)[2],
    float& us, float& r, float rs, float gn, float t2, float Bc, float ed)
{
    float ugr = 0.0f;
#pragma unroll
    for (int j = 0; j < 2; j++) {
        ugr = fmaf(uv[j].x, g[j].x, ugr);
        ugr = fmaf(uv[j].y, g[j].y, ugr);
        ugr = fmaf(uv[j].z, g[j].z, ugr);
        ugr = fmaf(uv[j].w, g[j].w, ugr);
    }
    ugr = grp_sum8(ugr);

    float ude  = -(us * ugr) * rs;            // u_true . grad_e
    float A2   = (ude - 1.0f) * t2;
    float opu  = 1.0f + ude;
    float A    = opu + A2;
    bool  cond = ude > -0.999f;
    float Bs   = cond ? Bc * us : 0.0f;                  // coeff on u_raw
    float Cc   = cond ? fmaf(Bc, ude, -A) * rs : rs;     // coeff on g

    float nsq = 0.0f;
#pragma unroll
    for (int j = 0; j < 2; j++) {
        float un;
        un = fmaf(Cc, g[j].x, Bs * uv[j].x); uv[j].x = un; nsq = fmaf(un, un, nsq);
        un = fmaf(Cc, g[j].y, Bs * uv[j].y); uv[j].y = un; nsq = fmaf(un, un, nsq);
        un = fmaf(Cc, g[j].z, Bs * uv[j].z); uv[j].z = un; nsq = fmaf(un, un, nsq);
        un = fmaf(Cc, g[j].w, Bs * uv[j].w); uv[j].w = un; nsq = fmaf(un, un, nsq);
    }
    nsq = grp_sum8(nsq);
    us  = rsqrtf(fmaxf(nsq, 1e-20f));         // u_true = us * u_raw

    float Z  = opu - A2;
    float dr = cond ? fmaf(ed, gn, __logf(0.5f * fmaxf(Z, 1e-10f)))
                    : -ed * gn;
    r += dr;
}

__global__ __launch_bounds__(256, 4)
void esh_kernel(const float* __restrict__ x0,
                const float* __restrict__ u0,
                const float* __restrict__ prec,
                const float* __restrict__ eps_p,
                const int* __restrict__ nsteps_p,
                float* __restrict__ out,
                int B)
{
    const int tid  = threadIdx.x;
    const int lane = tid & 31;
    const int p    = lane & 7;       // lane within group (8 per row)
    const int grp  = lane >> 3;      // 0..3 : row within warp
    const int warp = tid >> 5;       // 0..7
    const int row  = blockIdx.x * 32 + warp * 4 + grp;
    if (row >= B) return;

    const float eps = *eps_p;
    const int n_steps = *nsteps_p;
    const float ed = (0.5f * eps) * (1.0f / 64.0f);  // e/d, e = eps/2

    float4 xv[2], uv[2], pv[2];
    {
        const float4* xp = reinterpret_cast<const float4*>(x0 + (size_t)row * 64);
        const float4* up = reinterpret_cast<const float4*>(u0 + (size_t)row * 64);
        const float4* pp = reinterpret_cast<const float4*>(prec);
#pragma unroll
        for (int j = 0; j < 2; j++) {
            xv[j] = xp[p + 8 * j];
            uv[j] = up[p + 8 * j];
            pv[j] = pp[p + 8 * j];
        }
    }
    float r = 0.0f;
    float us = 1.0f;   // u_true = us * uv

    const size_t rowstride = (size_t)B * 64;
    const size_t XN = (size_t)(n_steps + 1) * rowstride;
    float* outr = out + 2 * XN + row;

    // step 0: x0, u0, r0=0
    float4* ox = reinterpret_cast<float4*>(out + (size_t)row * 64);
    float4* ou = reinterpret_cast<float4*>(out + XN + (size_t)row * 64);
#pragma unroll
    for (int j = 0; j < 2; j++) {
        __stcs(&ox[p + 8 * j], xv[j]);
        __stcs(&ou[p + 8 * j], uv[j]);
    }
    if (p == 0) __stcs(outr, 0.0f);

    const size_t f4stride = rowstride / 4;  // float4 elements per step

    // gradient state at current x (reused across step boundary)
    float4 g[2];
    float rs, gn, t2, Bc;
    compute_g(xv, pv, g, rs, gn, t2, Bc, ed);

    for (int s = 1; s <= n_steps; s++) {
        // first half-step: uses g at undrifted x (carried over)
        update_ur(g, uv, us, r, rs, gn, t2, Bc, ed);

        // drift: x += eps * u_true ; x is final for this step -> store now
        {
            const float c = eps * us;
#pragma unroll
            for (int j = 0; j < 2; j++) {
                xv[j].x = fmaf(c, uv[j].x, xv[j].x);
                xv[j].y = fmaf(c, uv[j].y, xv[j].y);
                xv[j].z = fmaf(c, uv[j].z, xv[j].z);
                xv[j].w = fmaf(c, uv[j].w, xv[j].w);
            }
        }
        ox += f4stride;
#pragma unroll
        for (int j = 0; j < 2; j++) __stcs(&ox[p + 8 * j], xv[j]);

        // gradient at drifted x (also serves next iteration's first half-step)
        compute_g(xv, pv, g, rs, gn, t2, Bc, ed);

        // second half-step
        update_ur(g, uv, us, r, rs, gn, t2, Bc, ed);

        ou += f4stride;
        outr += B;
        // materialize normalized u and store
#pragma unroll
        for (int j = 0; j < 2; j++) {
            float4 w;
            w.x = us * uv[j].x; w.y = us * uv[j].y;
            w.z = us * uv[j].z; w.w = us * uv[j].w;
            uv[j] = w;
            __stcs(&ou[p + 8 * j], w);
        }
        us = 1.0f;
        if (p == 0) __stcs(outr, r);
    }
}

extern "C" void kernel_launch(void* const* d_in, const int* in_sizes, int n_in,
                              void* d_out, int out_size)
{
    const float* x0     = (const float*)d_in[0];
    const float* u0     = (const float*)d_in[1];
    const float* prec   = (const float*)d_in[2];
    const float* eps_p  = (const float*)d_in[3];
    const int*   nsteps = (const int*)d_in[4];
    float* out = (float*)d_out;

    int B = in_sizes[0] / 64;
    int rows_per_block = 32;  // 256 threads, 8 warps, 4 rows/warp
    int grid = (B + rows_per_block - 1) / rows_per_block;
    esh_kernel<<<grid, 256>>>(x0, u0, prec, eps_p, nsteps, out, B);
}

// round 11
// speedup vs baseline: 1.4017x; 1.0118x over previous
#include <cuda_runtime.h>

// ESH sampler: B rows, D=64, n_steps of 2 half-steps each.
// Layout: 8 lanes per row (group), 4 rows per warp, 8 elems (2 float4) per lane.
// Lane-in-group p owns float4 chunks {p, p+8}.
//
// Elementwise math uses packed f32x2 (fma.rn.f32x2 / mul.rn.f32x2, PTX-only on
// sm_103a) — 2 fp32 ops per instruction, halving FMA-pipe issue and reduction
// chain depth. Grad reused across the step boundary (same x), u carried
// unnormalized with scalar scale `us`, x stored right after the drift.

using u64t = unsigned long long;

__device__ __forceinline__ u64t mul2(u64t a, u64t b) {
    u64t d; asm("mul.rn.f32x2 %0, %1, %2;" : "=l"(d) : "l"(a), "l"(b)); return d;
}
__device__ __forceinline__ u64t fma2(u64t a, u64t b, u64t c) {
    u64t d; asm("fma.rn.f32x2 %0, %1, %2, %3;" : "=l"(d) : "l"(a), "l"(b), "l"(c)); return d;
}
__device__ __forceinline__ u64t pack2(float lo, float hi) {
    u64t d; asm("mov.b64 %0, {%1, %2};" : "=l"(d) : "f"(lo), "f"(hi)); return d;
}
__device__ __forceinline__ float2 unpack2(u64t q) {
    float lo, hi; asm("mov.b64 {%0, %1}, %2;" : "=f"(lo), "=f"(hi) : "l"(q));
    return make_float2(lo, hi);
}

union Q2F { ulonglong2 q; float4 f; };

__device__ __forceinline__ float grp_sum8(float v) {
    v += __shfl_xor_sync(0xffffffffu, v, 1);
    v += __shfl_xor_sync(0xffffffffu, v, 2);
    v += __shfl_xor_sync(0xffffffffu, v, 4);
    return v;
}

// g = prec*x (packed) and all scalars that depend only on g.
__device__ __forceinline__ void compute_g(
    const u64t (&xq)[4], const u64t (&pq)[4],
    u64t (&gq)[4], float& rs, float& gn, float& t2, float& Bc, float ed)
{
    u64t gsq2 = 0ull;   // two packed +0.0f
#pragma unroll
    for (int k = 0; k < 4; k++) {
        gq[k] = mul2(pq[k], xq[k]);
        gsq2  = fma2(gq[k], gq[k], gsq2);
    }
    float2 s = unpack2(gsq2);
    float gsq = grp_sum8(s.x + s.y);
    rs = rsqrtf(fmaxf(gsq, 1e-20f));     // == 1/||g||
    gn = fminf(gsq * rs, 10.0f);         // clamped norm
    float t = __expf(-ed * gn);          // exp(-e*g/d)
    t2 = t * t;
    Bc = 2.0f * t;
}

// Momentum/r update given precomputed g and scalars.
__device__ __forceinline__ void update_ur(
    const u64t (&gq)[4], u64t (&uq)[4],
    float& us, float& r, float rs, float gn, float t2, float Bc, float ed)
{
    u64t ug2 = 0ull;
#pragma unroll
    for (int k = 0; k < 4; k++) ug2 = fma2(uq[k], gq[k], ug2);
    float2 su = unpack2(ug2);
    float ugr = grp_sum8(su.x + su.y);

    float ude  = -(us * ugr) * rs;            // u_true . grad_e
    float A2   = (ude - 1.0f) * t2;
    float opu  = 1.0f + ude;
    float A    = opu + A2;
    bool  cond = ude > -0.999f;
    float Bs   = cond ? Bc * us : 0.0f;                  // coeff on u_raw
    float Cc   = cond ? fmaf(Bc, ude, -A) * rs : rs;     // coeff on g

    u64t bs2 = pack2(Bs, Bs);
    u64t cc2 = pack2(Cc, Cc);
    u64t nsq2 = 0ull;
#pragma unroll
    for (int k = 0; k < 4; k++) {
        u64t un = fma2(cc2, gq[k], mul2(bs2, uq[k]));
        uq[k] = un;
        nsq2 = fma2(un, un, nsq2);
    }
    float2 sn = unpack2(nsq2);
    float nsq = grp_sum8(sn.x + sn.y);
    us = rsqrtf(fmaxf(nsq, 1e-20f));          // u_true = us * u_raw

    float Z  = opu - A2;
    float dr = cond ? fmaf(ed, gn, __logf(0.5f * fmaxf(Z, 1e-10f)))
                    : -ed * gn;
    r += dr;
}

__global__ __launch_bounds__(256, 4)
void esh_kernel(const float* __restrict__ x0,
                const float* __restrict__ u0,
                const float* __restrict__ prec,
                const float* __restrict__ eps_p,
                const int* __restrict__ nsteps_p,
                float* __restrict__ out,
                int B)
{
    const int tid  = threadIdx.x;
    const int lane = tid & 31;
    const int p    = lane & 7;       // lane within group (8 per row)
    const int grp  = lane >> 3;      // 0..3 : row within warp
    const int warp = tid >> 5;       // 0..7
    const int row  = blockIdx.x * 32 + warp * 4 + grp;
    if (row >= B) return;

    const float eps = *eps_p;
    const int n_steps = *nsteps_p;
    const float ed = (0.5f * eps) * (1.0f / 64.0f);  // e/d, e = eps/2

    // state: 8 floats/lane per array = 4 packed f32x2 regs
    u64t xq[4], uq[4], pq[4];
    {
        const ulonglong2* xp = reinterpret_cast<const ulonglong2*>(x0 + (size_t)row * 64);
        const ulonglong2* up = reinterpret_cast<const ulonglong2*>(u0 + (size_t)row * 64);
        const ulonglong2* pp = reinterpret_cast<const ulonglong2*>(prec);
#pragma unroll
        for (int j = 0; j < 2; j++) {
            ulonglong2 a = xp[p + 8 * j]; xq[2 * j] = a.x; xq[2 * j + 1] = a.y;
            ulonglong2 b = up[p + 8 * j]; uq[2 * j] = b.x; uq[2 * j + 1] = b.y;
            ulonglong2 c = pp[p + 8 * j]; pq[2 * j] = c.x; pq[2 * j + 1] = c.y;
        }
    }
    float r = 0.0f;
    float us = 1.0f;   // u_true = us * uq

    const size_t rowstride = (size_t)B * 64;
    const size_t XN = (size_t)(n_steps + 1) * rowstride;
    float* outr = out + 2 * XN + row;

    float4* ox = reinterpret_cast<float4*>(out + (size_t)row * 64);
    float4* ou = reinterpret_cast<float4*>(out + XN + (size_t)row * 64);

    // step 0: x0, u0, r0=0
#pragma unroll
    for (int j = 0; j < 2; j++) {
        Q2F tx; tx.q.x = xq[2 * j]; tx.q.y = xq[2 * j + 1];
        Q2F tu; tu.q.x = uq[2 * j]; tu.q.y = uq[2 * j + 1];
        __stcs(&ox[p + 8 * j], tx.f);
        __stcs(&ou[p + 8 * j], tu.f);
    }
    if (p == 0) __stcs(outr, 0.0f);

    const size_t f4stride = rowstride / 4;  // float4 elements per step

    // gradient state at current x (reused across step boundary)
    u64t gq[4];
    float rs, gn, t2, Bc;
    compute_g(xq, pq, gq, rs, gn, t2, Bc, ed);

    for (int s = 1; s <= n_steps; s++) {
        // first half-step: uses g at undrifted x (carried over)
        update_ur(gq, uq, us, r, rs, gn, t2, Bc, ed);

        // drift: x += eps * u_true ; x is final for this step -> store now
        {
            const float c = eps * us;
            const u64t c2 = pack2(c, c);
#pragma unroll
            for (int k = 0; k < 4; k++) xq[k] = fma2(c2, uq[k], xq[k]);
        }
        ox += f4stride;
#pragma unroll
        for (int j = 0; j < 2; j++) {
            Q2F tx; tx.q.x = xq[2 * j]; tx.q.y = xq[2 * j + 1];
            __stcs(&ox[p + 8 * j], tx.f);
        }

        // gradient at drifted x (also serves next iteration's first half-step)
        compute_g(xq, pq, gq, rs, gn, t2, Bc, ed);

        // second half-step
        update_ur(gq, uq, us, r, rs, gn, t2, Bc, ed);

        ou += f4stride;
        outr += B;
        // materialize normalized u and store
        {
            const u64t us2 = pack2(us, us);
#pragma unroll
            for (int k = 0; k < 4; k++) uq[k] = mul2(uq[k], us2);
#pragma unroll
            for (int j = 0; j < 2; j++) {
                Q2F tu; tu.q.x = uq[2 * j]; tu.q.y = uq[2 * j + 1];
                __stcs(&ou[p + 8 * j], tu.f);
            }
        }
        us = 1.0f;
        if (p == 0) __stcs(outr, r);
    }
}

extern "C" void kernel_launch(void* const* d_in, const int* in_sizes, int n_in,
                              void* d_out, int out_size)
{
    const float* x0     = (const float*)d_in[0];
    const float* u0     = (const float*)d_in[1];
    const float* prec   = (const float*)d_in[2];
    const float* eps_p  = (const float*)d_in[3];
    const int*   nsteps = (const int*)d_in[4];
    float* out = (float*)d_out;

    int B = in_sizes[0] / 64;
    int rows_per_block = 32;  // 256 threads, 8 warps, 4 rows/warp
    int grid = (B + rows_per_block - 1) / rows_per_block;
    esh_kernel<<<grid, 256>>>(x0, u0, prec, eps_p, nsteps, out, B);
}